// round 11
// baseline (speedup 1.0000x reference)
#include <cuda_runtime.h>

#define N_NODES 50000
#define D_FEAT 64
#define HIDDEN 128
#define N_EDGES 800000

// ---- scratch (__device__ globals; no cudaMalloc allowed) ----
__device__ __align__(16) float g_neigh[N_NODES * D_FEAT];
__device__ unsigned g_count[N_NODES];
__device__ unsigned g_off[N_NODES + 1];
__device__ unsigned g_cur[N_NODES];
__device__ int g_sorted_src[N_EDGES];

__global__ void zero_counts() {
    int i = blockIdx.x * blockDim.x + threadIdx.x;
    if (i < N_NODES) g_count[i] = 0u;
}

__global__ void hist(const int* __restrict__ ei) {
    int e = blockIdx.x * blockDim.x + threadIdx.x;
    if (e < N_EDGES) atomicAdd(&g_count[ei[N_EDGES + e]], 1u);
}

// Single-block exclusive scan over 50K counts -> off[] and cur[].
__global__ void scan_kernel() {
    const int T = 1024;
    const int PER = (N_NODES + T - 1) / T;  // 49
    __shared__ unsigned s[T];
    int t = threadIdx.x;
    int base = t * PER;

    unsigned local = 0;
    #pragma unroll 4
    for (int i = 0; i < PER; i++) {
        int idx = base + i;
        if (idx < N_NODES) local += g_count[idx];
    }
    s[t] = local;
    __syncthreads();

    // Hillis-Steele inclusive scan over per-thread sums.
    for (int off = 1; off < T; off <<= 1) {
        unsigned u = (t >= off) ? s[t - off] : 0u;
        __syncthreads();
        s[t] += u;
        __syncthreads();
    }

    unsigned run = s[t] - local;  // exclusive base for this thread's chunk
    for (int i = 0; i < PER; i++) {
        int idx = base + i;
        if (idx < N_NODES) {
            unsigned c = g_count[idx];
            g_off[idx] = run;
            g_cur[idx] = run;
            run += c;
        }
    }
    if (t == T - 1) g_off[N_NODES] = run;
}

__global__ void place(const int* __restrict__ ei) {
    int e = blockIdx.x * blockDim.x + threadIdx.x;
    if (e >= N_EDGES) return;
    int src = ei[e];
    int dst = ei[N_EDGES + e];
    unsigned idx = atomicAdd(&g_cur[dst], 1u);
    g_sorted_src[idx] = src;
}

// 16 lanes per node; lane owns one float4 chunk; register accumulate, one store.
__global__ void aggregate(const float* __restrict__ x) {
    int tid = blockIdx.x * blockDim.x + threadIdx.x;
    int node = tid >> 4;
    if (node >= N_NODES) return;
    int c = tid & 15;

    unsigned jb = g_off[node];
    unsigned je = g_off[node + 1];
    const float4* x4 = reinterpret_cast<const float4*>(x);

    float4 acc = make_float4(0.f, 0.f, 0.f, 0.f);
    #pragma unroll 4
    for (unsigned j = jb; j < je; j++) {
        int s = g_sorted_src[j];
        float4 v = x4[s * 16 + c];
        acc.x += v.x; acc.y += v.y; acc.z += v.z; acc.w += v.w;
    }
    reinterpret_cast<float4*>(g_neigh)[node * 16 + c] = acc;
}

// ---------------- fused concat + GEMM + bias + ReLU ----------------
#define TM 64
#define HPAD 68
#define WPAD 132

extern __shared__ float smem[];

__device__ __forceinline__ unsigned long long bcast_f32x2(float a) {
    unsigned long long r;
    asm("mov.b64 %0, {%1, %1};" : "=l"(r) : "f"(a));
    return r;
}

__global__ void __launch_bounds__(256, 2) fused_gemm(
    const float* __restrict__ x, const float* __restrict__ W,
    const float* __restrict__ b, float* __restrict__ out)
{
    float* sW = smem;               // [128][WPAD]  sW[k][o]
    float* sH = smem + 128 * WPAD;  // [128][HPAD]  sH[k][node]

    int tid  = threadIdx.x;
    int lane = tid & 31;
    int warp = tid >> 5;
    int nodeBase = blockIdx.x * TM;

    for (int c = warp; c < 32; c += 8) {
        #pragma unroll
        for (int ob = 0; ob < 128; ob += 32) {
            int o = ob + lane;
            float4 v = reinterpret_cast<const float4*>(W)[o * 32 + c];
            sW[(4 * c + 0) * WPAD + o] = v.x;
            sW[(4 * c + 1) * WPAD + o] = v.y;
            sW[(4 * c + 2) * WPAD + o] = v.z;
            sW[(4 * c + 3) * WPAD + o] = v.w;
        }
    }

    for (int c = warp; c < 32; c += 8) {
        const float4* srcp = (c < 16) ? reinterpret_cast<const float4*>(x)
                                      : reinterpret_cast<const float4*>(g_neigh);
        #pragma unroll
        for (int nb = 0; nb < TM; nb += 32) {
            int node = nodeBase + nb + lane;
            float4 v;
            if (node < N_NODES) v = srcp[node * 16 + (c & 15)];
            else                v = make_float4(0.f, 0.f, 0.f, 0.f);
            int n = nb + lane;
            sH[(4 * c + 0) * HPAD + n] = v.x;
            sH[(4 * c + 1) * HPAD + n] = v.y;
            sH[(4 * c + 2) * HPAD + n] = v.z;
            sH[(4 * c + 3) * HPAD + n] = v.w;
        }
    }
    __syncthreads();

    int tx = tid & 15;   // outs [tx*8, tx*8+8)
    int ty = tid >> 4;   // nodes [ty*4, ty*4+4)

    unsigned long long acc[4][4];
    #pragma unroll
    for (int i = 0; i < 4; i++)
        #pragma unroll
        for (int jp = 0; jp < 4; jp++) acc[i][jp] = 0ull;

    const float* sHrow = &sH[ty * 4];
    const float* sWrow = &sW[tx * 8];

    #pragma unroll 4
    for (int k = 0; k < 128; k++) {
        float4 h = *reinterpret_cast<const float4*>(sHrow + k * HPAD);
        ulonglong2 wa = *reinterpret_cast<const ulonglong2*>(sWrow + k * WPAD);
        ulonglong2 wb = *reinterpret_cast<const ulonglong2*>(sWrow + k * WPAD + 4);
        unsigned long long wv[4] = {wa.x, wa.y, wb.x, wb.y};
        float hv[4] = {h.x, h.y, h.z, h.w};
        #pragma unroll
        for (int i = 0; i < 4; i++) {
            unsigned long long hp = bcast_f32x2(hv[i]);
            #pragma unroll
            for (int jp = 0; jp < 4; jp++)
                asm("fma.rn.f32x2 %0, %1, %2, %0;"
                    : "+l"(acc[i][jp]) : "l"(hp), "l"(wv[jp]));
        }
    }

    float bias[8];
    #pragma unroll
    for (int j = 0; j < 8; j++) bias[j] = b[tx * 8 + j];

    #pragma unroll
    for (int i = 0; i < 4; i++) {
        int node = nodeBase + ty * 4 + i;
        if (node < N_NODES) {
            float r[8];
            #pragma unroll
            for (int jp = 0; jp < 4; jp++) {
                float lo, hi;
                asm("mov.b64 {%0, %1}, %2;" : "=f"(lo), "=f"(hi) : "l"(acc[i][jp]));
                float v0 = lo + bias[2 * jp];
                float v1 = hi + bias[2 * jp + 1];
                r[2 * jp]     = v0 > 0.f ? v0 : 0.f;
                r[2 * jp + 1] = v1 > 0.f ? v1 : 0.f;
            }
            float4* op = reinterpret_cast<float4*>(out + (size_t)node * HIDDEN + tx * 8);
            op[0] = make_float4(r[0], r[1], r[2], r[3]);
            op[1] = make_float4(r[4], r[5], r[6], r[7]);
        }
    }
}

extern "C" void kernel_launch(void* const* d_in, const int* in_sizes, int n_in,
                              void* d_out, int out_size) {
    const float* x  = (const float*)d_in[0];
    const int*   ei = (const int*)d_in[1];   // int32 (JAX x64 disabled)
    const float* W  = (const float*)d_in[2];
    const float* b  = (const float*)d_in[3];
    float*       out = (float*)d_out;

    zero_counts<<<(N_NODES + 255) / 256, 256>>>();
    hist<<<(N_EDGES + 255) / 256, 256>>>(ei);
    scan_kernel<<<1, 1024>>>();
    place<<<(N_EDGES + 255) / 256, 256>>>(ei);
    aggregate<<<(N_NODES * 16 + 255) / 256, 256>>>(x);

    int smem_bytes = (128 * WPAD + 128 * HPAD) * (int)sizeof(float);
    cudaFuncSetAttribute(fused_gemm,
                         cudaFuncAttributeMaxDynamicSharedMemorySize, smem_bytes);
    fused_gemm<<<(N_NODES + TM - 1) / TM, 256, smem_bytes>>>(x, W, b, out);
}

// round 12
// speedup vs baseline: 1.0020x; 1.0020x over previous
#include <cuda_runtime.h>

#define N_NODES 50000
#define D_FEAT 64
#define HIDDEN 128
#define N_EDGES 800000

// ---- scratch (__device__ globals; no cudaMalloc allowed) ----
__device__ __align__(16) float g_neigh[N_NODES * D_FEAT];
__device__ unsigned g_count[N_NODES];
__device__ unsigned g_off[N_NODES + 1];
__device__ unsigned g_cur[N_NODES];
__device__ int g_sorted_src[N_EDGES];

__global__ void zero_counts() {
    int i = blockIdx.x * blockDim.x + threadIdx.x;
    if (i < N_NODES) g_count[i] = 0u;
}

__global__ void hist(const int* __restrict__ ei) {
    int e = blockIdx.x * blockDim.x + threadIdx.x;
    if (e < N_EDGES) atomicAdd(&g_count[ei[N_EDGES + e]], 1u);
}

// Single-block exclusive scan over 50K counts -> off[] and cur[].
__global__ void scan_kernel() {
    const int T = 1024;
    const int PER = (N_NODES + T - 1) / T;  // 49
    __shared__ unsigned s[T];
    int t = threadIdx.x;
    int base = t * PER;

    unsigned local = 0;
    #pragma unroll 4
    for (int i = 0; i < PER; i++) {
        int idx = base + i;
        if (idx < N_NODES) local += g_count[idx];
    }
    s[t] = local;
    __syncthreads();

    // Hillis-Steele inclusive scan over per-thread sums.
    for (int off = 1; off < T; off <<= 1) {
        unsigned u = (t >= off) ? s[t - off] : 0u;
        __syncthreads();
        s[t] += u;
        __syncthreads();
    }

    unsigned run = s[t] - local;  // exclusive base for this thread's chunk
    for (int i = 0; i < PER; i++) {
        int idx = base + i;
        if (idx < N_NODES) {
            unsigned c = g_count[idx];
            g_off[idx] = run;
            g_cur[idx] = run;
            run += c;
        }
    }
    if (t == T - 1) g_off[N_NODES] = run;
}

__global__ void place(const int* __restrict__ ei) {
    int e = blockIdx.x * blockDim.x + threadIdx.x;
    if (e >= N_EDGES) return;
    int src = ei[e];
    int dst = ei[N_EDGES + e];
    unsigned idx = atomicAdd(&g_cur[dst], 1u);
    g_sorted_src[idx] = src;
}

// 16 lanes per node; lane owns one float4 chunk; register accumulate, one store.
__global__ void aggregate(const float* __restrict__ x) {
    int tid = blockIdx.x * blockDim.x + threadIdx.x;
    int node = tid >> 4;
    if (node >= N_NODES) return;
    int c = tid & 15;

    unsigned jb = g_off[node];
    unsigned je = g_off[node + 1];
    const float4* x4 = reinterpret_cast<const float4*>(x);

    float4 acc = make_float4(0.f, 0.f, 0.f, 0.f);
    #pragma unroll 4
    for (unsigned j = jb; j < je; j++) {
        int s = g_sorted_src[j];
        float4 v = x4[s * 16 + c];
        acc.x += v.x; acc.y += v.y; acc.z += v.z; acc.w += v.w;
    }
    reinterpret_cast<float4*>(g_neigh)[node * 16 + c] = acc;
}

// ---------------- fused concat + GEMM + bias + ReLU ----------------
#define TM 64
#define HPAD 68
#define WPAD 132

extern __shared__ float smem[];

__device__ __forceinline__ unsigned long long bcast_f32x2(float a) {
    unsigned long long r;
    asm("mov.b64 %0, {%1, %1};" : "=l"(r) : "f"(a));
    return r;
}

__global__ void __launch_bounds__(256, 2) fused_gemm(
    const float* __restrict__ x, const float* __restrict__ W,
    const float* __restrict__ b, float* __restrict__ out)
{
    float* sW = smem;               // [128][WPAD]  sW[k][o]
    float* sH = smem + 128 * WPAD;  // [128][HPAD]  sH[k][node]

    int tid  = threadIdx.x;
    int lane = tid & 31;
    int warp = tid >> 5;
    int nodeBase = blockIdx.x * TM;

    for (int c = warp; c < 32; c += 8) {
        #pragma unroll
        for (int ob = 0; ob < 128; ob += 32) {
            int o = ob + lane;
            float4 v = reinterpret_cast<const float4*>(W)[o * 32 + c];
            sW[(4 * c + 0) * WPAD + o] = v.x;
            sW[(4 * c + 1) * WPAD + o] = v.y;
            sW[(4 * c + 2) * WPAD + o] = v.z;
            sW[(4 * c + 3) * WPAD + o] = v.w;
        }
    }

    for (int c = warp; c < 32; c += 8) {
        const float4* srcp = (c < 16) ? reinterpret_cast<const float4*>(x)
                                      : reinterpret_cast<const float4*>(g_neigh);
        #pragma unroll
        for (int nb = 0; nb < TM; nb += 32) {
            int node = nodeBase + nb + lane;
            float4 v;
            if (node < N_NODES) v = srcp[node * 16 + (c & 15)];
            else                v = make_float4(0.f, 0.f, 0.f, 0.f);
            int n = nb + lane;
            sH[(4 * c + 0) * HPAD + n] = v.x;
            sH[(4 * c + 1) * HPAD + n] = v.y;
            sH[(4 * c + 2) * HPAD + n] = v.z;
            sH[(4 * c + 3) * HPAD + n] = v.w;
        }
    }
    __syncthreads();

    int tx = tid & 15;   // outs [tx*8, tx*8+8)
    int ty = tid >> 4;   // nodes [ty*4, ty*4+4)

    unsigned long long acc[4][4];
    #pragma unroll
    for (int i = 0; i < 4; i++)
        #pragma unroll
        for (int jp = 0; jp < 4; jp++) acc[i][jp] = 0ull;

    const float* sHrow = &sH[ty * 4];
    const float* sWrow = &sW[tx * 8];

    #pragma unroll 4
    for (int k = 0; k < 128; k++) {
        float4 h = *reinterpret_cast<const float4*>(sHrow + k * HPAD);
        ulonglong2 wa = *reinterpret_cast<const ulonglong2*>(sWrow + k * WPAD);
        ulonglong2 wb = *reinterpret_cast<const ulonglong2*>(sWrow + k * WPAD + 4);
        unsigned long long wv[4] = {wa.x, wa.y, wb.x, wb.y};
        float hv[4] = {h.x, h.y, h.z, h.w};
        #pragma unroll
        for (int i = 0; i < 4; i++) {
            unsigned long long hp = bcast_f32x2(hv[i]);
            #pragma unroll
            for (int jp = 0; jp < 4; jp++)
                asm("fma.rn.f32x2 %0, %1, %2, %0;"
                    : "+l"(acc[i][jp]) : "l"(hp), "l"(wv[jp]));
        }
    }

    float bias[8];
    #pragma unroll
    for (int j = 0; j < 8; j++) bias[j] = b[tx * 8 + j];

    #pragma unroll
    for (int i = 0; i < 4; i++) {
        int node = nodeBase + ty * 4 + i;
        if (node < N_NODES) {
            float r[8];
            #pragma unroll
            for (int jp = 0; jp < 4; jp++) {
                float lo, hi;
                asm("mov.b64 {%0, %1}, %2;" : "=f"(lo), "=f"(hi) : "l"(acc[i][jp]));
                float v0 = lo + bias[2 * jp];
                float v1 = hi + bias[2 * jp + 1];
                r[2 * jp]     = v0 > 0.f ? v0 : 0.f;
                r[2 * jp + 1] = v1 > 0.f ? v1 : 0.f;
            }
            float4* op = reinterpret_cast<float4*>(out + (size_t)node * HIDDEN + tx * 8);
            op[0] = make_float4(r[0], r[1], r[2], r[3]);
            op[1] = make_float4(r[4], r[5], r[6], r[7]);
        }
    }
}

extern "C" void kernel_launch(void* const* d_in, const int* in_sizes, int n_in,
                              void* d_out, int out_size) {
    const float* x  = (const float*)d_in[0];
    const int*   ei = (const int*)d_in[1];   // int32 (JAX x64 disabled)
    const float* W  = (const float*)d_in[2];
    const float* b  = (const float*)d_in[3];
    float*       out = (float*)d_out;

    zero_counts<<<(N_NODES + 255) / 256, 256>>>();
    hist<<<(N_EDGES + 255) / 256, 256>>>(ei);
    scan_kernel<<<1, 1024>>>();
    place<<<(N_EDGES + 255) / 256, 256>>>(ei);
    aggregate<<<(N_NODES * 16 + 255) / 256, 256>>>(x);

    int smem_bytes = (128 * WPAD + 128 * HPAD) * (int)sizeof(float);
    cudaFuncSetAttribute(fused_gemm,
                         cudaFuncAttributeMaxDynamicSharedMemorySize, smem_bytes);
    fused_gemm<<<(N_NODES + TM - 1) / TM, 256, smem_bytes>>>(x, W, b, out);
}